// round 12
// baseline (speedup 1.0000x reference)
#include <cuda_runtime.h>
#include <math.h>

#define NMAX 100000
#define GRID 148
#define TPB  1024

__device__ float    g_diag[NMAX];
__device__ unsigned g_deg[NMAX];
__device__ unsigned g_bar;          // device-wide barrier counter

// ---------------------------------------------------------------------------
// K0: zero degree counters + barrier (runs every replay, before mega)
// ---------------------------------------------------------------------------
__global__ void k_zero(int n4) {
    int i = blockIdx.x * blockDim.x + threadIdx.x;
    if (i < n4) ((uint4*)g_deg)[i] = make_uint4(0u, 0u, 0u, 0u);
    if (i == 0) g_bar = 0u;
}

// ---------------------------------------------------------------------------
// K1: diag[i] = sigmoid(dot(x[i,:], w) + b).  2 rows per warp, D=256.
// ---------------------------------------------------------------------------
__global__ void k_diag(const float* __restrict__ x,
                       const float* __restrict__ w,
                       const float* __restrict__ b,
                       int n) {
    __shared__ float4 ws[64];
    int t = threadIdx.x;
    if (t < 64) ws[t] = ((const float4*)w)[t];
    __syncthreads();

    int lane = t & 31;
    int warp = blockIdx.x * (blockDim.x >> 5) + (t >> 5);
    int row0 = warp << 1;
    if (row0 >= n) return;
    bool has1 = (row0 + 1) < n;

    const float4* xr0 = (const float4*)(x + (size_t)row0 * 256);
    const float4* xr1 = (const float4*)(x + (size_t)(row0 + 1) * 256);

    float4 a0 = xr0[lane];
    float4 a1 = xr0[lane + 32];
    float4 c0, c1;
    if (has1) { c0 = xr1[lane]; c1 = xr1[lane + 32]; }
    else      { c0 = make_float4(0,0,0,0); c1 = c0; }

    float4 w0 = ws[lane];
    float4 w1 = ws[lane + 32];

    float s0 = a0.x*w0.x + a0.y*w0.y + a0.z*w0.z + a0.w*w0.w
             + a1.x*w1.x + a1.y*w1.y + a1.z*w1.z + a1.w*w1.w;
    float s1 = c0.x*w0.x + c0.y*w0.y + c0.z*w0.z + c0.w*w0.w
             + c1.x*w1.x + c1.y*w1.y + c1.z*w1.z + c1.w*w1.w;

#pragma unroll
    for (int o = 16; o; o >>= 1) {
        s0 += __shfl_xor_sync(0xffffffffu, s0, o);
        s1 += __shfl_xor_sync(0xffffffffu, s1, o);
    }
    if (lane == 0) {
        float bb = b[0];
        g_diag[row0] = 1.0f / (1.0f + expf(-(s0 + bb)));
        if (has1) g_diag[row0 + 1] = 1.0f / (1.0f + expf(-(s1 + bb)));
    }
}

// ---------------------------------------------------------------------------
// K2: persistent mega-kernel. One CTA per SM (co-resident by construction:
//     grid=148 <= 152 SMs, ~173KB smem/CTA -> 1 CTA/SM).
//     Phase 1: read ei once -> smem (r,c), idx->float copy out, deg atomics.
//     Device-wide barrier (counter pre-zeroed by k_zero on same stream).
//     Phase 2: val[e] = attr[e] * diag[c] * rcp(deg[r]) from smem (r,c).
// ---------------------------------------------------------------------------
extern __shared__ int s_rc[];   // [per] rows, then [per] cols

__global__ void __launch_bounds__(TPB, 1)
k_mega(const int* __restrict__ ei,
       const float* __restrict__ attr,
       float* __restrict__ out_idx,
       float* __restrict__ outv,
       int E, int per, int write_idx) {
    const int base = blockIdx.x * per;
    const int end  = min(base + per, E);
    const int cnt  = end - base;
    int* sr = s_rc;
    int* sc = s_rc + per;

    // ---- Phase 1: stream edges, stash in smem, count degrees, copy idx ----
    for (int k = threadIdx.x; k < cnt; k += TPB) {
        int e = base + k;
        int r = ei[e];
        int c = ei[E + e];
        sr[k] = r;
        sc[k] = c;
        if (write_idx) {
            out_idx[e]     = (float)r;
            out_idx[E + e] = (float)c;
        }
        if ((unsigned)c < NMAX) atomicAdd(&g_deg[c], 1u);
    }

    // ---- Device-wide barrier ----
    __threadfence();               // make my atomics/stores visible
    __syncthreads();
    if (threadIdx.x == 0) {
        unsigned me = atomicAdd(&g_bar, 1u) + 1u;
        if (me < gridDim.x) {
            while (*(volatile unsigned*)&g_bar < gridDim.x)
                __nanosleep(64);
        }
    }
    __syncthreads();
    __threadfence();               // acquire: see all CTAs' deg updates

    // ---- Phase 2: values from smem-cached (r,c) ----
    for (int k = threadIdx.x; k < cnt; k += TPB) {
        int e = base + k;
        int r = sr[k];
        int c = sc[k];
        float dg = ((unsigned)c < NMAX) ? g_diag[c] : 0.0f;
        unsigned du = ((unsigned)r < NMAX) ? g_deg[r] : 1u;
        outv[e] = attr[e] * dg * __frcp_rn(__uint2float_rn(du));
    }
}

// ---------------------------------------------------------------------------
static bool g_init = false;

extern "C" void kernel_launch(void* const* d_in, const int* in_sizes, int n_in,
                              void* d_out, int out_size) {
    const float* x    = (const float*)d_in[0];
    const int*   ei   = (const int*)d_in[1];     // int32 (2, E)
    const float* attr = (const float*)d_in[2];
    const float* w    = (const float*)d_in[3];
    const float* b    = (const float*)d_in[4];

    const int E  = in_sizes[2];
    const int Dd = in_sizes[3];
    const int n  = in_sizes[0] / Dd;

    const int per = (E + GRID - 1) / GRID;              // edges per CTA
    const size_t smem = 2 * (size_t)per * sizeof(int);  // ~173KB for E=3.2M

    if (!g_init) {
        cudaFuncSetAttribute(k_mega,
            cudaFuncAttributeMaxDynamicSharedMemorySize, (int)smem);
        g_init = true;
    }

    float* out = (float*)d_out;
    float* out_vals;
    int write_idx;
    if (out_size >= 3 * E) {      // [edge_index(2E) | vals(E)] as float32
        write_idx = 1;
        out_vals = out + 2 * (size_t)E;
    } else {
        write_idx = 0;
        out_vals = out;
    }

    const int T = 256;
    const int n4 = (n + 3) >> 2;

    // serial on the capture stream — overlap across kernels doesn't pay
    k_zero<<<(n4 + T - 1) / T, T>>>(n4);
    k_diag<<<(n / 2 + 7) / 8, T>>>(x, w, b, n);
    k_mega<<<GRID, TPB, smem>>>(ei, attr, out, out_vals, E, per, write_idx);
}

// round 13
// speedup vs baseline: 1.6668x; 1.6668x over previous
#include <cuda_runtime.h>
#include <math.h>

#define NMAX 100000

__device__ float    g_diag[NMAX];
__device__ unsigned g_deg[NMAX];

// ---------------------------------------------------------------------------
// K0: zero degree counters
// ---------------------------------------------------------------------------
__global__ void k_zero(int n4) {
    int i = blockIdx.x * blockDim.x + threadIdx.x;
    if (i < n4) ((uint4*)g_deg)[i] = make_uint4(0u, 0u, 0u, 0u);
}

// ---------------------------------------------------------------------------
// K1 (heterogeneous): interleaved diag-GEMV blocks and deg+copy blocks.
//   diag block: 8 warps x 2 rows = 16 rows of x (DRAM-bound)
//   deg  block: 256 threads x int4 = 1024 edges (LTS-atomic-bound + copy)
//   Pattern (when GDIAG == 2*GDEG): bid%3<2 -> diag, bid%3==2 -> deg.
// ---------------------------------------------------------------------------
__global__ void __launch_bounds__(256)
k_fused(const float* __restrict__ x,
        const float* __restrict__ w,
        const float* __restrict__ b,
        int n,
        const int* __restrict__ ei,
        float* __restrict__ out_idx,
        int E, int E4, int write_idx,
        int GDIAG, int GDEG, int interleave) {
    int bid = blockIdx.x;
    int is_diag, sub;
    if (interleave) {
        int g3 = bid / 3, r3 = bid - g3 * 3;
        if (bid < 3 * GDEG) {
            if (r3 < 2) { is_diag = 1; sub = g3 * 2 + r3; }
            else        { is_diag = 0; sub = g3; }
        } else {
            is_diag = 1; sub = 2 * GDEG + (bid - 3 * GDEG);
        }
    } else {
        if (bid < GDIAG) { is_diag = 1; sub = bid; }
        else             { is_diag = 0; sub = bid - GDIAG; }
    }

    if (is_diag) {
        // ---------------- diag portion ----------------
        if (sub >= GDIAG) return;
        __shared__ float4 ws[64];
        int t = threadIdx.x;
        if (t < 64) ws[t] = ((const float4*)w)[t];
        __syncthreads();

        int lane = t & 31;
        int warp = sub * 8 + (t >> 5);
        int row0 = warp << 1;
        if (row0 >= n) return;
        bool has1 = (row0 + 1) < n;

        const float4* xr0 = (const float4*)(x + (size_t)row0 * 256);
        const float4* xr1 = (const float4*)(x + (size_t)(row0 + 1) * 256);

        float4 a0 = xr0[lane];
        float4 a1 = xr0[lane + 32];
        float4 c0, c1;
        if (has1) { c0 = xr1[lane]; c1 = xr1[lane + 32]; }
        else      { c0 = make_float4(0,0,0,0); c1 = c0; }

        float4 w0 = ws[lane];
        float4 w1 = ws[lane + 32];

        float s0 = a0.x*w0.x + a0.y*w0.y + a0.z*w0.z + a0.w*w0.w
                 + a1.x*w1.x + a1.y*w1.y + a1.z*w1.z + a1.w*w1.w;
        float s1 = c0.x*w0.x + c0.y*w0.y + c0.z*w0.z + c0.w*w0.w
                 + c1.x*w1.x + c1.y*w1.y + c1.z*w1.z + c1.w*w1.w;

#pragma unroll
        for (int o = 16; o; o >>= 1) {
            s0 += __shfl_xor_sync(0xffffffffu, s0, o);
            s1 += __shfl_xor_sync(0xffffffffu, s1, o);
        }
        if (lane == 0) {
            float bb = b[0];
            g_diag[row0] = 1.0f / (1.0f + expf(-(s0 + bb)));
            if (has1) g_diag[row0 + 1] = 1.0f / (1.0f + expf(-(s1 + bb)));
        }
    } else {
        // ---------------- deg + idx-copy portion ----------------
        int i = sub * 256 + threadIdx.x;
        if (i >= E4) return;
        int4 c = ((const int4*)(ei + E))[i];
        if (write_idx) {
            int4 r = ((const int4*)ei)[i];
            ((float4*)out_idx)[i] =
                make_float4((float)r.x, (float)r.y, (float)r.z, (float)r.w);
            ((float4*)(out_idx + E))[i] =
                make_float4((float)c.x, (float)c.y, (float)c.z, (float)c.w);
        }
        if ((unsigned)c.x < NMAX) atomicAdd(&g_deg[c.x], 1u);
        if ((unsigned)c.y < NMAX) atomicAdd(&g_deg[c.y], 1u);
        if ((unsigned)c.z < NMAX) atomicAdd(&g_deg[c.z], 1u);
        if ((unsigned)c.w < NMAX) atomicAdd(&g_deg[c.w], 1u);
    }
}

// ---------------------------------------------------------------------------
// K2: val[e] = attr[e] * diag[col] * rcp((float)deg[row])
// ---------------------------------------------------------------------------
__global__ void k_val(const int* __restrict__ ei,
                      const float* __restrict__ attr,
                      float* __restrict__ outv,
                      int E4, int E) {
    int i = blockIdx.x * blockDim.x + threadIdx.x;
    if (i >= E4) return;

    int4 r = ((const int4*)ei)[i];
    int4 c = ((const int4*)(ei + E))[i];
    float4 a = ((const float4*)attr)[i];

    unsigned u0 = ((unsigned)r.x < NMAX) ? g_deg[r.x] : 1u;
    unsigned u1 = ((unsigned)r.y < NMAX) ? g_deg[r.y] : 1u;
    unsigned u2 = ((unsigned)r.z < NMAX) ? g_deg[r.z] : 1u;
    unsigned u3 = ((unsigned)r.w < NMAX) ? g_deg[r.w] : 1u;
    float g0 = ((unsigned)c.x < NMAX) ? g_diag[c.x] : 0.0f;
    float g1 = ((unsigned)c.y < NMAX) ? g_diag[c.y] : 0.0f;
    float g2 = ((unsigned)c.z < NMAX) ? g_diag[c.z] : 0.0f;
    float g3 = ((unsigned)c.w < NMAX) ? g_diag[c.w] : 0.0f;

    float4 v;
    v.x = a.x * g0 * __frcp_rn(__uint2float_rn(u0));
    v.y = a.y * g1 * __frcp_rn(__uint2float_rn(u1));
    v.z = a.z * g2 * __frcp_rn(__uint2float_rn(u2));
    v.w = a.w * g3 * __frcp_rn(__uint2float_rn(u3));
    ((float4*)outv)[i] = v;
}

// ---------------------------------------------------------------------------
extern "C" void kernel_launch(void* const* d_in, const int* in_sizes, int n_in,
                              void* d_out, int out_size) {
    const float* x    = (const float*)d_in[0];
    const int*   ei   = (const int*)d_in[1];     // int32 (2, E)
    const float* attr = (const float*)d_in[2];
    const float* w    = (const float*)d_in[3];
    const float* b    = (const float*)d_in[4];

    const int E  = in_sizes[2];
    const int Dd = in_sizes[3];
    const int n  = in_sizes[0] / Dd;

    float* out = (float*)d_out;
    float* out_vals;
    int write_idx;
    if (out_size >= 3 * E) {      // [edge_index(2E) | vals(E)] as float32
        write_idx = 1;
        out_vals = out + 2 * (size_t)E;
    } else {
        write_idx = 0;
        out_vals = out;
    }

    const int T = 256;
    const int E4 = E >> 2;
    const int n4 = (n + 3) >> 2;

    const int GDIAG = (n + 15) / 16;          // 16 rows per diag block
    const int GDEG  = (E4 + T - 1) / T;       // 1024 edges per deg block
    const int interleave = (GDIAG == 2 * GDEG);
    const int GRID = GDIAG + GDEG;

    k_zero<<<(n4 + T - 1) / T, T>>>(n4);
    k_fused<<<GRID, T>>>(x, w, b, n, ei, out, E, E4, write_idx,
                         GDIAG, GDEG, interleave);
    k_val<<<(E4 + T - 1) / T, T>>>(ei, attr, out_vals, E4, E);
}